// round 17
// baseline (speedup 1.0000x reference)
#include <cuda_runtime.h>

#define NN 100000
#define EE 3200000
#define FIN 512
#define HH 16
#define CC 40
#define CAP 128            // bucket capacity per node (deg~Poisson(32), 17-sigma safe)
#define KCH 4              // gemm1 K-split chunks
#define RB  391            // row-blocks in gemm1 = ceil(NN/256)
#define SB  3125           // scatter blocks (EE / 1024)
#define FUSED_GRID 4692    // 1564 gemm (bi%3==0) + 3128 scatter slots

typedef unsigned long long u64;

// ---------------- scratch (device globals; no allocation allowed) ----------
__device__ u64   g_pack[NN];         // (slots<<40) | fixed24(sum ew)
__device__ float g_dinv[NN];
__device__ __align__(16) int2  g_csr[NN * CAP];     // {row, ew_bits}, bucketed
__device__ __align__(16) float g_part[KCH * NN * HH];
__device__ __align__(16) float g_bufA[NN * HH];
__device__ __align__(16) float g_bufB[NN * HH];

// ---------------- packed f32x2 helpers -------------------------------------
__device__ __forceinline__ void ffma2(u64& d, u64 a, u64 b) {
    asm("fma.rn.f32x2 %0, %1, %2, %0;" : "+l"(d) : "l"(a), "l"(b));
}
__device__ __forceinline__ u64 add2(u64 a, u64 b) {
    u64 r; asm("add.rn.f32x2 %0, %1, %2;" : "=l"(r) : "l"(a), "l"(b)); return r;
}
__device__ __forceinline__ u64 pack2(float a, float b) {
    u64 r; asm("mov.b64 %0, {%1, %2};" : "=l"(r) : "f"(a), "f"(b)); return r;
}
__device__ __forceinline__ float2 unpack2(u64 v) {
    float2 r; asm("mov.b64 {%0, %1}, %2;" : "=f"(r.x), "=f"(r.y) : "l"(v)); return r;
}

// ---------------- init: zero pack -------------------------------------------
__global__ void k_init() {
    int i = blockIdx.x * blockDim.x + threadIdx.x;
    if (i < NN) g_pack[i] = 0ull;
}

// ---------------- FUSED: scatter + gemm1 (independent work, one launch) ----
// bi%3==0  -> gemm1 block   (bid = bi/3, 0..1563)
// bi%3!=0  -> scatter block (sid = 2*(bi/3)+(bi%3)-1, 0..3127; >=SB idle)
// gemm body is software-pipelined: tile t+1's LDGs issue before tile t computes.
__global__ __launch_bounds__(256, 4) void k_fused(const float* __restrict__ x,
                                                  const float* __restrict__ W,
                                                  const int*   __restrict__ ei,
                                                  const float* __restrict__ ew) {
    __shared__ float Ws[128 * 16];                  // gemm W slice, 8 KB
    __shared__ __align__(16) float xs[2][256 * 18]; // double-buffered staging
    int bi = blockIdx.x;
    int t = threadIdx.x;

    if (bi % 3 != 0) {
        // ---------------- scatter body ----------------
        int sid = (bi / 3) * 2 + (bi % 3) - 1;
        if (sid >= SB) return;
        int e4 = (sid * 256 + t) * 4;
        int4   r = *(const int4*)(ei + e4);
        int4   c = *(const int4*)(ei + EE + e4);
        float4 w = *(const float4*)(ew + e4);
        u64 p, old;
        p = (1ull << 40) | (u64)__float2uint_rn(w.x * 16777216.0f);
        old = atomicAdd(&g_pack[c.x], p);
        g_csr[(c.x << 7) + (int)(old >> 40)] = make_int2(r.x, __float_as_int(w.x));
        p = (1ull << 40) | (u64)__float2uint_rn(w.y * 16777216.0f);
        old = atomicAdd(&g_pack[c.y], p);
        g_csr[(c.y << 7) + (int)(old >> 40)] = make_int2(r.y, __float_as_int(w.y));
        p = (1ull << 40) | (u64)__float2uint_rn(w.z * 16777216.0f);
        old = atomicAdd(&g_pack[c.z], p);
        g_csr[(c.z << 7) + (int)(old >> 40)] = make_int2(r.z, __float_as_int(w.z));
        p = (1ull << 40) | (u64)__float2uint_rn(w.w * 16777216.0f);
        old = atomicAdd(&g_pack[c.w], p);
        g_csr[(c.w << 7) + (int)(old >> 40)] = make_int2(r.w, __float_as_int(w.w));
        return;
    }

    // ---------------- gemm1 body (f-split warps, W in smem, pipelined) -----
    int bid = bi / 3;
    int lane = t & 31;
    int w = t >> 5;
    int khalf = w & 1;
    int rg = (w >> 1) & 1;                       // row half (128 rows)
    int fh = w >> 2;                             // f half of tile
    int rbase = rg * 128 + lane;                 // local row of rr=0
    int rowblk = bid % RB;
    int chunk  = bid / RB;                       // K-chunk of 128 feats
    int rowbase = rowblk * 256;

    // stage W chunk slice once: 128 rows x 16 cols = 2048 floats
    {
        const float4* W4 = (const float4*)(W + chunk * 128 * 16);
        float4* Ws4 = (float4*)Ws;
        Ws4[t]       = W4[t];
        Ws4[t + 256] = W4[t + 256];
    }

    u64 acc[4][4];
#pragma unroll
    for (int rr = 0; rr < 4; rr++)
#pragma unroll
        for (int q = 0; q < 4; q++) acc[rr][q] = 0ull;

    const float4* x4 = (const float4*)x;
    int srow = t >> 2, sf4 = t & 3;              // this thread's staging slot
    int sgrow = rowbase + srow;                  // rows srow, +64, +128, +192

    // prologue: load tile 0 into regs, store to buffer 0
    float4 pf[4];
#pragma unroll
    for (int i = 0; i < 4; i++) {
        int grow = sgrow + i * 64;
        pf[i] = make_float4(0.f, 0.f, 0.f, 0.f);
        if (grow < NN) pf[i] = x4[grow * (FIN / 4) + chunk * 32 + sf4];
    }
#pragma unroll
    for (int i = 0; i < 4; i++) {
        float* dst = &xs[0][(srow + i * 64) * 18 + sf4 * 4];
        *(float2*)(dst)     = make_float2(pf[i].x, pf[i].y);
        *(float2*)(dst + 2) = make_float2(pf[i].z, pf[i].w);
    }
    __syncthreads();

    for (int tile = 0; tile < 8; tile++) {       // 8 x 16 = 128 feats
        int cb = tile & 1, nb = cb ^ 1;
        // issue next tile's loads BEFORE compute (overlap DRAM with FFMA)
        if (tile < 7) {
            int fbase4 = chunk * 32 + (tile + 1) * 4;
#pragma unroll
            for (int i = 0; i < 4; i++) {
                int grow = sgrow + i * 64;
                pf[i] = make_float4(0.f, 0.f, 0.f, 0.f);
                if (grow < NN) pf[i] = x4[grow * (FIN / 4) + fbase4 + sf4];
            }
        }
        // compute tile from current buffer
#pragma unroll
        for (int f2i = 0; f2i < 4; f2i++) {
            int f2 = fh * 4 + f2i;               // f-pair 0..7
            int fo = (tile * 16 + f2 * 2) * 16 + khalf * 8;
            ulonglong2 w00 = *(const ulonglong2*)(Ws + fo);       // f even
            ulonglong2 w01 = *(const ulonglong2*)(Ws + fo + 4);
            ulonglong2 w10 = *(const ulonglong2*)(Ws + fo + 16);  // f odd
            ulonglong2 w11 = *(const ulonglong2*)(Ws + fo + 20);
#pragma unroll
            for (int rr = 0; rr < 4; rr++) {
                float2 xv = *(const float2*)(&xs[cb][(rbase + rr * 32) * 18 + f2 * 2]);
                u64 x0 = pack2(xv.x, xv.x);
                u64 x1 = pack2(xv.y, xv.y);
                ffma2(acc[rr][0], x0, w00.x); ffma2(acc[rr][1], x0, w00.y);
                ffma2(acc[rr][2], x0, w01.x); ffma2(acc[rr][3], x0, w01.y);
                ffma2(acc[rr][0], x1, w10.x); ffma2(acc[rr][1], x1, w10.y);
                ffma2(acc[rr][2], x1, w11.x); ffma2(acc[rr][3], x1, w11.y);
            }
        }
        // store prefetched tile to alternate buffer, then one sync
        if (tile < 7) {
#pragma unroll
            for (int i = 0; i < 4; i++) {
                float* dst = &xs[nb][(srow + i * 64) * 18 + sf4 * 4];
                *(float2*)(dst)     = make_float2(pf[i].x, pf[i].y);
                *(float2*)(dst + 2) = make_float2(pf[i].z, pf[i].w);
            }
        }
        __syncthreads();
    }

    // reduce fh pairs: fh1 stores partials, fh0 adds
    u64* red = (u64*)xs[0];                      // 128 threads x 16 u64 = 16KB
    int t128 = t & 127;
    if (fh == 1) {
#pragma unroll
        for (int rr = 0; rr < 4; rr++)
#pragma unroll
            for (int q = 0; q < 4; q++) red[t128 * 16 + rr * 4 + q] = acc[rr][q];
    }
    __syncthreads();
    if (fh == 0) {
        float4* out4 = (float4*)(g_part + chunk * NN * HH);
#pragma unroll
        for (int rr = 0; rr < 4; rr++) {
            int row = rowbase + rbase + rr * 32;
            if (row < NN) {
                u64 s0 = add2(acc[rr][0], red[t128 * 16 + rr * 4 + 0]);
                u64 s1 = add2(acc[rr][1], red[t128 * 16 + rr * 4 + 1]);
                u64 s2 = add2(acc[rr][2], red[t128 * 16 + rr * 4 + 2]);
                u64 s3 = add2(acc[rr][3], red[t128 * 16 + rr * 4 + 3]);
                float2 a = unpack2(s0); float2 b = unpack2(s1);
                float2 c = unpack2(s2); float2 d = unpack2(s3);
                out4[row * 4 + khalf * 2 + 0] = make_float4(a.x, a.y, b.x, b.y);
                out4[row * 4 + khalf * 2 + 1] = make_float4(c.x, c.y, d.x, d.y);
            }
        }
    }
}

// ---------------- gemm1 reduce + dinv + CSR zero-padding -------------------
// bufA = dinv * relu(sum parts + b); also pads each bucket to 16-multiple
// with {row=0, ew=0} entries so k_agg needs no bounds checks.
__global__ __launch_bounds__(256) void k_gfin(const float* __restrict__ b) {
    int idx = blockIdx.x * 256 + threadIdx.x;      // float4 index
    if (idx >= NN * 4) return;
    const float4* p = (const float4*)g_part;
    float4 p0 = p[idx];
    float4 p1 = p[idx + NN * 4];
    float4 p2 = p[idx + NN * 8];
    float4 p3 = p[idx + NN * 12];
    int row = idx >> 2, k4 = idx & 3;
    float4 bb = __ldg(&((const float4*)b)[k4]);
    u64 pk = g_pack[row];
    float deg = 1.0f + (float)(pk & 0xFFFFFFFFFFull) * 5.9604645e-8f;
    float dv = rsqrtf(deg);
    if (k4 == 0) g_dinv[row] = dv;
    float4 o;
    o.x = fmaxf(p0.x + p1.x + p2.x + p3.x + bb.x, 0.f) * dv;
    o.y = fmaxf(p0.y + p1.y + p2.y + p3.y + bb.y, 0.f) * dv;
    o.z = fmaxf(p0.z + p1.z + p2.z + p3.z + bb.z, 0.f) * dv;
    o.w = fmaxf(p0.w + p1.w + p2.w + p3.w + bb.w, 0.f) * dv;
    ((float4*)g_bufA)[idx] = o;

    // zero-pad bucket [cnt, cnt16): 4 threads stride the <=15 pad slots
    int cnt = (int)(pk >> 40);
    int cnt16 = (cnt + 15) & ~15;
    int2* bucket = g_csr + (row << 7);
#pragma unroll
    for (int j = 0; j < 4; j++) {
        int s = cnt + k4 + j * 4;
        if (s < cnt16) bucket[s] = make_int2(0, 0);
    }
}

// ---------------- fused conv: hout = [dinv*] relu((A @ hin) @ W + b) -------
// hin pre-scaled by dinv; buckets zero-padded to 16 -> branch-free loop.
// half-warp per node; dual accumulators break the FFMA chain.
__global__ __launch_bounds__(256) void k_agg(const float* __restrict__ hin,
                                             float* __restrict__ hout,
                                             const float* __restrict__ W,
                                             const float* __restrict__ bias,
                                             int premul) {
    __shared__ float Ws[256];
    __shared__ float bs[16];
    __shared__ float hb[256];
    Ws[threadIdx.x] = W[threadIdx.x];
    if (threadIdx.x < 16) bs[threadIdx.x] = bias[threadIdx.x];
    __syncthreads();

    int tid = blockIdx.x * 256 + threadIdx.x;     // grid = NN*16/256 exactly
    int node = tid >> 4;
    int k = tid & 15;

    int cnt16 = ((int)(g_pack[node] >> 40) + 15) & ~15;
    float acc0 = hin[node * 16 + k];              // self loop (already scaled)
    float acc1 = 0.f;

    const int4* bp = (const int4*)(g_csr + (node << 7));  // 2 edges per int4
    for (int e = 0; e < cnt16; e += 16) {
        const int4* cp = bp + (e >> 1);
#pragma unroll
        for (int j = 0; j < 8; j++) {
            int4 pq = __ldg(&cp[j]);
            acc0 += __int_as_float(pq.y) * __ldg(&hin[pq.x * 16 + k]);
            acc1 += __int_as_float(pq.w) * __ldg(&hin[pq.z * 16 + k]);
        }
    }
    float dv = g_dinv[node];
    float acc = (acc0 + acc1) * dv;

    // 16x16 transform: exchange aggregated feats within the half-warp
    hb[threadIdx.x] = acc;
    __syncwarp();
    int hbase = threadIdx.x & ~15;
    float o = bs[k];
#pragma unroll
    for (int f = 0; f < 16; f++) o += hb[hbase + f] * Ws[f * 16 + k];
    float res = fmaxf(o, 0.0f);
    if (premul) res *= dv;                        // pre-scale for next layer
    hout[node * 16 + k] = res;
}

// ---------------- output: logits (16x40) + log_softmax --------------------
__global__ __launch_bounds__(256) void k_out(const float* __restrict__ Wo,
                                             const float* __restrict__ bo,
                                             float* __restrict__ out) {
    __shared__ float Ws[16 * 40];
    __shared__ float bs[40];
    for (int i = threadIdx.x; i < 640; i += 256) Ws[i] = Wo[i];
    if (threadIdx.x < 40) bs[threadIdx.x] = bo[threadIdx.x];
    __syncthreads();
    int idx = blockIdx.x * blockDim.x + threadIdx.x;
    if (idx >= NN) return;

    const float4* in4 = (const float4*)g_bufA;
    float hx[16];
#pragma unroll
    for (int q = 0; q < 4; q++) {
        float4 v = in4[idx * 4 + q];
        hx[q * 4 + 0] = v.x; hx[q * 4 + 1] = v.y;
        hx[q * 4 + 2] = v.z; hx[q * 4 + 3] = v.w;
    }
    float acc[40];
#pragma unroll
    for (int c = 0; c < 40; c++) acc[c] = bs[c];
#pragma unroll
    for (int f = 0; f < 16; f++) {
        float xv = hx[f];
#pragma unroll
        for (int c = 0; c < 40; c++) acc[c] += xv * Ws[f * 40 + c];
    }
    float m = acc[0];
#pragma unroll
    for (int c = 1; c < 40; c++) m = fmaxf(m, acc[c]);
    float s = 0.f;
#pragma unroll
    for (int c = 0; c < 40; c++) s += __expf(acc[c] - m);
    float lse = m + __logf(s);
#pragma unroll
    for (int c = 0; c < 40; c++) out[idx * 40 + c] = acc[c] - lse;
}

// ---------------- launch ---------------------------------------------------
extern "C" void kernel_launch(void* const* d_in, const int* in_sizes, int n_in,
                              void* d_out, int out_size) {
    const float* x  = (const float*)d_in[0];
    const int*   ei = (const int*)d_in[1];     // int32! (JAX x64 disabled)
    const float* ew = (const float*)d_in[2];
    const float* Wf = (const float*)d_in[3];
    const float* bf = (const float*)d_in[4];
    const float* W1 = (const float*)d_in[5];
    const float* b1 = (const float*)d_in[6];
    const float* W2 = (const float*)d_in[7];
    const float* b2 = (const float*)d_in[8];
    const float* Wo = (const float*)d_in[9];
    const float* bo = (const float*)d_in[10];
    float* out = (float*)d_out;

    float* bufA; float* bufB;
    cudaGetSymbolAddress((void**)&bufA, g_bufA);
    cudaGetSymbolAddress((void**)&bufB, g_bufB);

    k_init   <<<(NN + 255) / 256, 256>>>();
    k_fused  <<<FUSED_GRID, 256>>>(x, Wf, ei, ew);
    k_gfin   <<<(NN * 4 + 255) / 256, 256>>>(bf);

    k_agg    <<<NN * 16 / 256, 256>>>(bufA, bufB, W1, b1, 1);
    k_agg    <<<NN * 16 / 256, 256>>>(bufB, bufA, W2, b2, 0);

    k_out    <<<(NN + 255) / 256, 256>>>(Wo, bo, out);
}